// round 2
// baseline (speedup 1.0000x reference)
#include <cuda_runtime.h>

#define NB 16
#define NC 64
#define HW 65536
#define NBINS 256
#define S1B 64          // mean blocks per batch (one per channel plane)
#define S2B 64          // cos/hist blocks per batch
#define S4B 1024        // mul blocks per batch
#define BPB (S1B + S2B + S4B)   // 1152 blocks per batch

// ---- scratch (no allocations allowed) ----
__device__ float         d_mean[NB * NC];
__device__ unsigned int  d_hist[NB * NBINS];
__device__ float         d_scale[NB * NBINS];
__device__ unsigned char d_q[NB * HW];
__device__ unsigned int  d_cnt1[NB];   // mean-done arrivals
__device__ unsigned int  d_cnt2[NB];   // cos-done arrivals (65 == LUT ready)

// ============================================================
// Init: zero flags + histograms each replay. grid=NB, 256 thr
// ============================================================
__global__ void k_init() {
    d_hist[blockIdx.x * NBINS + threadIdx.x] = 0u;
    if (threadIdx.x == 0) { d_cnt1[blockIdx.x] = 0u; d_cnt2[blockIdx.x] = 0u; }
}

__device__ __forceinline__ void spin_ge(const unsigned int* p, unsigned int v) {
    const volatile unsigned int* vp = (const volatile unsigned int*)p;
    while (*vp < v) __nanosleep(64);
}

// ============================================================
// Mega-kernel: per-batch [mean | cos+hist(+lut) | mul] pipeline
// ============================================================
__global__ void __launch_bounds__(256) k_mega(const float* __restrict__ F,
                                              float* __restrict__ out) {
    const int tid = threadIdx.x;
    const int b   = blockIdx.x / BPB;
    const int r   = blockIdx.x - b * BPB;

    __shared__ float        sA[NBINS];
    __shared__ float        sB[NBINS];
    __shared__ unsigned int sU[NBINS];
    __shared__ int          sLast;

    if (r < S1B) {
        // ---------- Stage 1: mean of plane (b, c=r) ----------
        const int c = r;
        const float4* p = (const float4*)F + ((size_t)(b * NC + c) * (HW / 4));
        float s = 0.f;
        #pragma unroll 8
        for (int j = 0; j < HW / 4 / 256; ++j) {
            float4 v = p[j * 256 + tid];
            s += (v.x + v.y) + (v.z + v.w);
        }
        sA[tid] = s;
        __syncthreads();
        for (int o = 128; o > 0; o >>= 1) {
            if (tid < o) sA[tid] += sA[tid + o];
            __syncthreads();
        }
        if (tid == 0) {
            d_mean[b * NC + c] = sA[0] * (1.0f / HW);
            __threadfence();
            atomicAdd(&d_cnt1[b], 1u);
        }
    } else if (r < S1B + S2B) {
        // ---------- Stage 2: cosine + quantize + histogram ----------
        const int blk = r - S1B;
        if (tid == 0) spin_ge(&d_cnt1[b], S1B);
        __syncthreads();
        __threadfence();                       // acquire d_mean

        if (tid < NC) sA[tid] = d_mean[b * NC + tid];
        sU[tid] = 0u;
        __syncthreads();
        sB[tid] = (tid < NC) ? sA[tid] * sA[tid] : 0.f;
        __syncthreads();
        for (int o = 128; o > 0; o >>= 1) {
            if (tid < o) sB[tid] += sB[tid + o];
            __syncthreads();
        }
        float inv = 1.0f / fmaxf(sqrtf(sB[0]), 1e-12f);
        __syncthreads();
        if (tid < NC) sA[tid] *= inv;          // a / max(||a||, eps)
        __syncthreads();

        const int p4 = blk * 256 + tid;        // float4 pixel index within batch
        const float4* p = (const float4*)F + ((size_t)b * NC * (HW / 4)) + p4;
        float d0 = 0.f, d1 = 0.f, d2 = 0.f, d3 = 0.f;
        float s0 = 0.f, s1 = 0.f, s2 = 0.f, s3 = 0.f;
        #pragma unroll 8
        for (int c = 0; c < NC; ++c) {
            float4 v = p[c * (HW / 4)];
            float ac = sA[c];
            d0 += ac * v.x; d1 += ac * v.y; d2 += ac * v.z; d3 += ac * v.w;
            s0 += v.x * v.x; s1 += v.y * v.y; s2 += v.z * v.z; s3 += v.w * v.w;
        }
        int q0 = ((int)((d0 / fmaxf(sqrtf(s0), 1e-12f)) * 255.0f)) & 255;
        int q1 = ((int)((d1 / fmaxf(sqrtf(s1), 1e-12f)) * 255.0f)) & 255;
        int q2 = ((int)((d2 / fmaxf(sqrtf(s2), 1e-12f)) * 255.0f)) & 255;
        int q3 = ((int)((d3 / fmaxf(sqrtf(s3), 1e-12f)) * 255.0f)) & 255;

        atomicAdd(&sU[q0], 1u); atomicAdd(&sU[q1], 1u);
        atomicAdd(&sU[q2], 1u); atomicAdd(&sU[q3], 1u);

        *(uchar4*)(d_q + ((size_t)b << 16) + ((size_t)p4 << 2)) =
            make_uchar4((unsigned char)q0, (unsigned char)q1,
                        (unsigned char)q2, (unsigned char)q3);

        __syncthreads();
        unsigned int cnt = sU[tid];
        if (cnt) atomicAdd(&d_hist[b * NBINS + tid], cnt);
        __syncthreads();

        if (tid == 0) {
            __threadfence();                   // release hist + q
            unsigned int old = atomicAdd(&d_cnt2[b], 1u);
            sLast = (old == S2B - 1);
        }
        __syncthreads();

        if (sLast) {
            // ---------- Stage 3 (last block only): build LUT ----------
            __threadfence();                   // acquire all hist
            float h = (float)d_hist[b * NBINS + tid];
            sA[tid] = h;
            __syncthreads();
            for (int o = 1; o < NBINS; o <<= 1) {   // inclusive scan
                float v = sA[tid];
                float add = (tid >= o) ? sA[tid - o] : 0.f;
                __syncthreads();
                sA[tid] = v + add;
                __syncthreads();
            }
            sB[tid] = (h > 0.f) ? sA[tid] : (float)(HW + 1);
            __syncthreads();
            for (int o = 128; o > 0; o >>= 1) {
                if (tid < o) sB[tid] = fminf(sB[tid], sB[tid + o]);
                __syncthreads();
            }
            float cmin  = sB[0];
            float denom = fmaxf((float)HW - cmin, 1.0f);
            float lut   = rintf((sA[tid] - cmin) * (255.0f / denom));
            lut = fminf(fmaxf(lut, 0.0f), 255.0f);
            d_scale[b * NBINS + tid] = lut * (1.0f / 255.0f);
            __syncthreads();
            if (tid == 0) {
                __threadfence();               // release scale
                atomicAdd(&d_cnt2[b], 1u);     // -> S2B + 1 : LUT ready
            }
        }
    } else {
        // ---------- Stage 4: out = F * scale[q] ----------
        const int blk = r - S1B - S2B;
        if (tid == 0) spin_ge(&d_cnt2[b], S2B + 1);
        __syncthreads();
        __threadfence();                       // acquire scale + q

        sA[tid] = d_scale[b * NBINS + tid];
        __syncthreads();

        const size_t base = (size_t)b * (NC * HW / 4) + (size_t)blk * 1024;
        const float4* Fp = (const float4*)F + base;
        float4*       Op = (float4*)out + base;
        const int p4base = (blk * 1024) & (HW / 4 - 1);  // block stays in one plane

        #pragma unroll
        for (int k = 0; k < 4; ++k) {
            int idx = k * 256 + tid;
            int p4  = p4base + idx;
            uchar4 q = *(const uchar4*)(d_q + ((size_t)b << 16) + ((size_t)p4 << 2));
            float4 v = __ldcs(Fp + idx);       // last use: evict-first
            float4 o;
            o.x = v.x * sA[q.x];
            o.y = v.y * sA[q.y];
            o.z = v.z * sA[q.z];
            o.w = v.w * sA[q.w];
            __stcs(Op + idx, o);               // streaming store: don't pollute L2
        }
    }
}

// ============================================================
extern "C" void kernel_launch(void* const* d_in, const int* in_sizes, int n_in,
                              void* d_out, int out_size) {
    const float* F = (const float*)d_in[0];
    float* out = (float*)d_out;
    (void)in_sizes; (void)n_in; (void)out_size;

    k_init<<<NB, NBINS>>>();
    k_mega<<<NB * BPB, 256>>>(F, out);
}

// round 3
// speedup vs baseline: 1.5285x; 1.5285x over previous
#include <cuda_runtime.h>

#define NB 16
#define NC 64
#define HW 65536
#define NBINS 256
#define GR 4                    // batches per group (64 MB slab, fits L2)
#define NGROUPS (NB / GR)       // 4
#define NBLK 592                // 148 SMs * 4 blocks, all co-resident

// ---- scratch (no allocations allowed) ----
__device__ float         d_mean[NB * NC];
__device__ unsigned int  d_hist[NB * NBINS];
__device__ float         d_scale[NB * NBINS];
__device__ unsigned char d_q[NB * HW];
__device__ unsigned int  d_lutready[NB];
__device__ unsigned int  g_cnt;
__device__ volatile unsigned int g_gen;

// ============================================================
// Init each replay: zero hists, flags, barrier state.
// ============================================================
__global__ void k_init() {
    d_hist[blockIdx.x * NBINS + threadIdx.x] = 0u;
    if (threadIdx.x == 0) {
        d_lutready[blockIdx.x] = 0u;
        if (blockIdx.x == 0) { g_cnt = 0u; g_gen = 0u; }
    }
}

// ---- grid-wide barrier (all NBLK blocks co-resident) ----
__device__ __forceinline__ void gbar() {
    __syncthreads();
    if (threadIdx.x == 0) {
        unsigned int my = g_gen;
        __threadfence();
        if (atomicAdd(&g_cnt, 1u) == NBLK - 1) {
            g_cnt = 0u;
            __threadfence();
            g_gen = my + 1u;
        } else {
            while (g_gen == my) __nanosleep(64);
        }
    }
    __syncthreads();
    __threadfence();
}

// ============================================================
// Persistent kernel: groups of GR batches, L2-resident slabs.
// ============================================================
__global__ void __launch_bounds__(256, 4) k_mega(const float* __restrict__ F,
                                                 float* __restrict__ out) {
    const int tid = threadIdx.x;
    const int p   = blockIdx.x;

    __shared__ float        sA[NBINS];
    __shared__ float        sB[NBINS];
    __shared__ unsigned int sU[NBINS];

    for (int g = 0; g < NGROUPS; ++g) {
        // ---------- Phase 1: per-plane mean (256 blocks, 1 plane each) ----------
        if (p < GR * NC) {
            const int batch = g * GR + (p >> 6);
            const int c     = p & 63;
            const float4* base = (const float4*)F + ((size_t)(batch * NC + c) << 14);
            float s = 0.f;
            #pragma unroll 8
            for (int j = 0; j < HW / 4 / 256; ++j) {
                float4 v = base[j * 256 + tid];
                s += (v.x + v.y) + (v.z + v.w);
            }
            sA[tid] = s;
            __syncthreads();
            for (int o = 128; o > 0; o >>= 1) {
                if (tid < o) sA[tid] += sA[tid + o];
                __syncthreads();
            }
            if (tid == 0) d_mean[batch * NC + c] = sA[0] * (1.0f / HW);
        }
        gbar();

        // ---------- Phase 2: cosine + quantize + histogram (256 blocks) --------
        if (p < GR * 64) {
            const int batch = g * GR + (p >> 6);
            const int chunk = p & 63;

            if (tid < NC) sA[tid] = d_mean[batch * NC + tid];
            sU[tid] = 0u;
            __syncthreads();
            sB[tid] = (tid < NC) ? sA[tid] * sA[tid] : 0.f;
            __syncthreads();
            for (int o = 128; o > 0; o >>= 1) {
                if (tid < o) sB[tid] += sB[tid + o];
                __syncthreads();
            }
            float inv = 1.0f / fmaxf(sqrtf(sB[0]), 1e-12f);
            __syncthreads();
            if (tid < NC) sA[tid] *= inv;
            __syncthreads();

            const int p4 = chunk * 256 + tid;       // float4 pixel index in batch
            const float4* fp = (const float4*)F + ((size_t)batch << 20) + p4;
            float d0 = 0.f, d1 = 0.f, d2 = 0.f, d3 = 0.f;
            float s0 = 0.f, s1 = 0.f, s2 = 0.f, s3 = 0.f;
            #pragma unroll 8
            for (int c = 0; c < NC; ++c) {
                float4 v = fp[c * (HW / 4)];
                float ac = sA[c];
                d0 += ac * v.x; d1 += ac * v.y; d2 += ac * v.z; d3 += ac * v.w;
                s0 += v.x * v.x; s1 += v.y * v.y; s2 += v.z * v.z; s3 += v.w * v.w;
            }
            int q0 = ((int)((d0 / fmaxf(sqrtf(s0), 1e-12f)) * 255.0f)) & 255;
            int q1 = ((int)((d1 / fmaxf(sqrtf(s1), 1e-12f)) * 255.0f)) & 255;
            int q2 = ((int)((d2 / fmaxf(sqrtf(s2), 1e-12f)) * 255.0f)) & 255;
            int q3 = ((int)((d3 / fmaxf(sqrtf(s3), 1e-12f)) * 255.0f)) & 255;

            atomicAdd(&sU[q0], 1u); atomicAdd(&sU[q1], 1u);
            atomicAdd(&sU[q2], 1u); atomicAdd(&sU[q3], 1u);

            *(uchar4*)(d_q + ((size_t)batch << 16) + ((size_t)p4 << 2)) =
                make_uchar4((unsigned char)q0, (unsigned char)q1,
                            (unsigned char)q2, (unsigned char)q3);

            __syncthreads();
            unsigned int cnt = sU[tid];
            if (cnt) atomicAdd(&d_hist[batch * NBINS + tid], cnt);
        }
        gbar();

        // ---------- Phase 3a: LUT per batch (GR blocks) ----------
        if (p < GR) {
            const int batch = g * GR + p;
            float h = (float)d_hist[batch * NBINS + tid];
            sA[tid] = h;
            __syncthreads();
            for (int o = 1; o < NBINS; o <<= 1) {       // inclusive scan
                float v = sA[tid];
                float add = (tid >= o) ? sA[tid - o] : 0.f;
                __syncthreads();
                sA[tid] = v + add;
                __syncthreads();
            }
            sB[tid] = (h > 0.f) ? sA[tid] : (float)(HW + 1);
            __syncthreads();
            for (int o = 128; o > 0; o >>= 1) {
                if (tid < o) sB[tid] = fminf(sB[tid], sB[tid + o]);
                __syncthreads();
            }
            float cmin  = sB[0];
            float denom = fmaxf((float)HW - cmin, 1.0f);
            float lut   = rintf((sA[tid] - cmin) * (255.0f / denom));
            lut = fminf(fmaxf(lut, 0.0f), 255.0f);
            d_scale[batch * NBINS + tid] = lut * (1.0f / 255.0f);
            __syncthreads();
            __threadfence();
            if (tid == 0) atomicExch(&d_lutready[batch], 1u);
        }

        // ---------- Phase 3b: out = F * scale[q] (all blocks) ----------
        for (int bi = 0; bi < GR; ++bi) {
            const int batch = g * GR + bi;
            if (tid == 0) {
                while (((volatile unsigned int*)d_lutready)[batch] == 0u)
                    __nanosleep(64);
            }
            __syncthreads();
            __threadfence();

            sA[tid] = d_scale[batch * NBINS + tid];
            __syncthreads();

            const int start = p * 1792;                  // 256-aligned chunk
            if (start < (1 << 20)) {
                const float4* Fb = (const float4*)F + ((size_t)batch << 20);
                float4*       Ob = (float4*)out + ((size_t)batch << 20);
                #pragma unroll
                for (int k = 0; k < 7; ++k) {
                    int idx = start + k * 256 + tid;
                    if (idx < (1 << 20)) {
                        int p4 = idx & 16383;
                        uchar4 q = *(const uchar4*)(d_q + ((size_t)batch << 16) +
                                                    ((size_t)p4 << 2));
                        float4 v = __ldcs(Fb + idx);
                        float4 o;
                        o.x = v.x * sA[q.x];
                        o.y = v.y * sA[q.y];
                        o.z = v.z * sA[q.z];
                        o.w = v.w * sA[q.w];
                        __stcs(Ob + idx, o);
                    }
                }
            }
            __syncthreads();    // sA reused next bi
        }
        // no barrier here: next group's mean has no dependency on this mul
    }
}

// ============================================================
extern "C" void kernel_launch(void* const* d_in, const int* in_sizes, int n_in,
                              void* d_out, int out_size) {
    const float* F = (const float*)d_in[0];
    float* out = (float*)d_out;
    (void)in_sizes; (void)n_in; (void)out_size;

    k_init<<<NB, NBINS>>>();
    k_mega<<<NBLK, 256>>>(F, out);
}

// round 5
// speedup vs baseline: 1.9137x; 1.2520x over previous
#include <cuda_runtime.h>

#define NB 16
#define NC 64
#define HW 65536
#define NBINS 256
#define NBLK 512                 // 4 cohorts x 128 blocks, all co-resident
#define COH 128                  // blocks per cohort (per batch)

// ---- scratch (no allocations allowed) ----
__device__ float         d_part[NB * NC * 2];   // two partial sums per plane
__device__ unsigned int  d_hist[NB * NBINS];
__device__ float         d_scale[NB * NBINS];
__device__ unsigned char d_q[NB * HW];
__device__ unsigned int  d_c1[NB];              // mean arrivals   (==128 ready)
__device__ unsigned int  d_c2[NB];              // cos arrivals    (==129 lut ready)

__global__ void k_init() {
    d_hist[blockIdx.x * NBINS + threadIdx.x] = 0u;
    if (threadIdx.x == 0) { d_c1[blockIdx.x] = 0u; d_c2[blockIdx.x] = 0u; }
}

// ============================================================
// Persistent kernel: 4 independent cohort pipelines.
// Cohort k handles batches k, k+4, k+8, k+12 end-to-end.
// ============================================================
__global__ void __launch_bounds__(256, 4) k_mega(const float* __restrict__ F,
                                                 float* __restrict__ out) {
    const int tid    = threadIdx.x;
    const int p      = blockIdx.x;
    const int cohort = p >> 7;          // 0..3
    const int sub    = p & 127;         // 0..127 within cohort

    __shared__ float        sPart[8 * 256];     // 8 KB: partials / reduce scratch
    __shared__ float        sA[NBINS];          // a-hat / scale table
    __shared__ unsigned int sU[NBINS];          // block histogram
    __shared__ int          sLast;

    for (int g = 0; g < 4; ++g) {
        const int b = g * 4 + cohort;

        // ---------------- Phase 1: plane means (2 blocks/plane) ----------------
        {
            const int c = sub >> 1, half = sub & 1;
            const float4* base = (const float4*)F +
                ((size_t)(b * NC + c) << 14) + ((size_t)half << 13);
            float s = 0.f;
            #pragma unroll 8
            for (int j = 0; j < 32; ++j) {                  // 8192 float4 / 256 thr
                float4 v = __ldcg(base + j * 256 + tid);    // L2-only first touch
                s += (v.x + v.y) + (v.z + v.w);
            }
            sPart[tid] = s;
            __syncthreads();
            for (int o = 128; o > 0; o >>= 1) {
                if (tid < o) sPart[tid] += sPart[tid + o];
                __syncthreads();
            }
            if (tid == 0) {
                d_part[(b * NC + c) * 2 + half] = sPart[0];
                __threadfence();
                atomicAdd(&d_c1[b], 1u);
            }
        }

        // wait all means of this batch
        if (tid == 0) { while (((volatile unsigned int*)d_c1)[b] < COH) __nanosleep(32); }
        __syncthreads();
        __threadfence();

        // a-hat: deterministic fixed-order combine of the two partials
        if (tid < NC)
            sA[tid] = (d_part[(b * NC + tid) * 2] + d_part[(b * NC + tid) * 2 + 1])
                      * (1.0f / HW);
        sU[tid] = 0u;
        __syncthreads();
        sPart[tid] = (tid < NC) ? sA[tid] * sA[tid] : 0.f;
        __syncthreads();
        for (int o = 128; o > 0; o >>= 1) {
            if (tid < o) sPart[tid] += sPart[tid + o];
            __syncthreads();
        }
        const float inv = 1.0f / fmaxf(sqrtf(sPart[0]), 1e-12f);
        __syncthreads();
        if (tid < NC) sA[tid] *= inv;
        __syncthreads();

        // ---------------- Phase 2: cosine + quantize + histogram ----------------
        {
            const int px = (sub << 7) + (tid & 127);        // float4-pixel index
            const int c0 = (tid >> 7) << 5;                 // channel half: 0 | 32
            const float4* fp = (const float4*)F + ((size_t)b << 20) + px;
            float d0 = 0.f, d1 = 0.f, d2 = 0.f, d3 = 0.f;
            float s0 = 0.f, s1 = 0.f, s2 = 0.f, s3 = 0.f;
            #pragma unroll 8
            for (int i = 0; i < 32; ++i) {
                float4 v = fp[(size_t)(c0 + i) << 14];
                float ac = sA[c0 + i];
                d0 += ac * v.x; d1 += ac * v.y; d2 += ac * v.z; d3 += ac * v.w;
                s0 += v.x * v.x; s1 += v.y * v.y; s2 += v.z * v.z; s3 += v.w * v.w;
            }
            sPart[0 * 256 + tid] = d0; sPart[1 * 256 + tid] = d1;
            sPart[2 * 256 + tid] = d2; sPart[3 * 256 + tid] = d3;
            sPart[4 * 256 + tid] = s0; sPart[5 * 256 + tid] = s1;
            sPart[6 * 256 + tid] = s2; sPart[7 * 256 + tid] = s3;
            __syncthreads();

            if (tid < 128) {
                float D0 = sPart[0 * 256 + tid] + sPart[0 * 256 + tid + 128];
                float D1 = sPart[1 * 256 + tid] + sPart[1 * 256 + tid + 128];
                float D2 = sPart[2 * 256 + tid] + sPart[2 * 256 + tid + 128];
                float D3 = sPart[3 * 256 + tid] + sPart[3 * 256 + tid + 128];
                float S0 = sPart[4 * 256 + tid] + sPart[4 * 256 + tid + 128];
                float S1 = sPart[5 * 256 + tid] + sPart[5 * 256 + tid + 128];
                float S2 = sPart[6 * 256 + tid] + sPart[6 * 256 + tid + 128];
                float S3 = sPart[7 * 256 + tid] + sPart[7 * 256 + tid + 128];
                int q0 = ((int)((D0 / fmaxf(sqrtf(S0), 1e-12f)) * 255.0f)) & 255;
                int q1 = ((int)((D1 / fmaxf(sqrtf(S1), 1e-12f)) * 255.0f)) & 255;
                int q2 = ((int)((D2 / fmaxf(sqrtf(S2), 1e-12f)) * 255.0f)) & 255;
                int q3 = ((int)((D3 / fmaxf(sqrtf(S3), 1e-12f)) * 255.0f)) & 255;
                atomicAdd(&sU[q0], 1u); atomicAdd(&sU[q1], 1u);
                atomicAdd(&sU[q2], 1u); atomicAdd(&sU[q3], 1u);
                const int mypx = (sub << 7) + tid;
                *(uchar4*)(d_q + ((size_t)b << 16) + ((size_t)mypx << 2)) =
                    make_uchar4((unsigned char)q0, (unsigned char)q1,
                                (unsigned char)q2, (unsigned char)q3);
            }
            __syncthreads();
            unsigned int cnt = sU[tid];
            if (cnt) atomicAdd(&d_hist[b * NBINS + tid], cnt);
            __syncthreads();

            if (tid == 0) {
                __threadfence();
                unsigned int old = atomicAdd(&d_c2[b], 1u);
                sLast = (old == COH - 1);
            }
            __syncthreads();

            if (sLast) {   // last cos block of this batch builds the LUT
                __threadfence();
                float h = (float)d_hist[b * NBINS + tid];
                float* cdf = sPart;
                float* tmp = sPart + 256;
                cdf[tid] = h;
                __syncthreads();
                for (int o = 1; o < NBINS; o <<= 1) {
                    float v = cdf[tid];
                    float add = (tid >= o) ? cdf[tid - o] : 0.f;
                    __syncthreads();
                    cdf[tid] = v + add;
                    __syncthreads();
                }
                tmp[tid] = (h > 0.f) ? cdf[tid] : (float)(HW + 1);
                __syncthreads();
                for (int o = 128; o > 0; o >>= 1) {
                    if (tid < o) tmp[tid] = fminf(tmp[tid], tmp[tid + o]);
                    __syncthreads();
                }
                float cmin  = tmp[0];
                float denom = fmaxf((float)HW - cmin, 1.0f);
                float lut   = rintf((cdf[tid] - cmin) * (255.0f / denom));
                lut = fminf(fmaxf(lut, 0.0f), 255.0f);
                d_scale[b * NBINS + tid] = lut * (1.0f / 255.0f);
                __syncthreads();
                if (tid == 0) {
                    __threadfence();
                    atomicAdd(&d_c2[b], 1u);        // -> 129 : LUT ready
                }
            }
        }

        // ---------------- Phase 3: out = F * scale[q] ----------------
        {
            if (tid == 0) { while (((volatile unsigned int*)d_c2)[b] < COH + 1) __nanosleep(32); }
            __syncthreads();
            __threadfence();

            sA[tid] = d_scale[b * NBINS + tid];
            __syncthreads();

            const float4* Fb = (const float4*)F + ((size_t)b << 20);
            float4*       Ob = (float4*)out + ((size_t)b << 20);
            const int base = sub << 13;                     // 8192 float4 per block
            #pragma unroll 4
            for (int k = 0; k < 32; ++k) {
                int idx = base + k * 256 + tid;
                int p4  = idx & 16383;
                uchar4 q = *(const uchar4*)(d_q + ((size_t)b << 16) + ((size_t)p4 << 2));
                float4 v = __ldcs(Fb + idx);    // last use: evict-first
                float4 o;
                o.x = v.x * sA[q.x];
                o.y = v.y * sA[q.y];
                o.z = v.z * sA[q.z];
                o.w = v.w * sA[q.w];
                __stcs(Ob + idx, o);            // streaming store
            }
        }
        __syncthreads();    // shared reuse next group iteration
    }
}

// ============================================================
extern "C" void kernel_launch(void* const* d_in, const int* in_sizes, int n_in,
                              void* d_out, int out_size) {
    const float* F = (const float*)d_in[0];
    float* out = (float*)d_out;
    (void)in_sizes; (void)n_in; (void)out_size;

    k_init<<<NB, NBINS>>>();
    k_mega<<<NBLK, 256>>>(F, out);
}